// round 12
// baseline (speedup 1.0000x reference)
#include <cuda_runtime.h>
#include <cuda_bf16.h>
#include <cstdint>

// ---------------------------------------------------------------------------
// Problem dims
// ---------------------------------------------------------------------------
#define BB    32
#define CIN   32
#define COUT  64
#define HH    128
#define WW    128
#define MAXCN 64
#define HO    126
#define WO    126
#define NPIX  (HO * WO)          // 15876
#define KTOT  (CIN * 9)          // 288
#define TILE_M 128
#define NT_PER_B ((NPIX + TILE_M - 1) / TILE_M)   // 125
#define NTILES (BB * NT_PER_B)                    // 4000
#define CH_PER_CHUNK 8
#define KCHUNK (CH_PER_CHUNK * 9)                 // 72
#define NCHUNK 4

#define WS_STRIDE 292     // floats per oc row
#define AS_STRIDE 76      // floats per px row
#define OFF_WS 0
#define OFF_AS (COUT * WS_STRIDE)                       // 18688 floats
#define AS_BUF_FLOATS (TILE_M * AS_STRIDE)              // 9728
#define OFF_PX (OFF_AS + 2 * AS_BUF_FLOATS)
#define SMEM_FLOATS (OFF_PX + TILE_M)
#define SMEM_TOTAL (SMEM_FLOATS * 4)                    // 153088 B

// Effective dense kernel scratch: [COUT][KTOT], k = c*9 + tap
__device__ float g_kd[COUT * KTOT];

// ---------------------------------------------------------------------------
// Kernel 1: fold padded kernel bank into dense [O, C*9]
// ---------------------------------------------------------------------------
__global__ void build_kdense(const float* __restrict__ w,
                             const int* __restrict__ cn) {
    int o = blockIdx.x;
    int t = threadIdx.x;
    if (t < KTOT) {
        int c = t / 9;
        int k = t % 9;
        int cnum = cn[o];
        float v = 0.f;
        if (c < cnum)        v += w[(o * MAXCN + c) * 9 + k];
        if (c + CIN < cnum)  v += w[(o * MAXCN + c + CIN) * 9 + k];
        g_kd[o * KTOT + t] = v;
    }
}

// ---------------------------------------------------------------------------
// helpers
// ---------------------------------------------------------------------------
__device__ __forceinline__ float to_tf32(float v) {
    uint32_t r;
    asm("cvt.rna.tf32.f32 %0, %1;" : "=r"(r) : "f"(v));
    return __uint_as_float(r);
}
__device__ __forceinline__ uint32_t cvt_rna_u32(float v) {
    uint32_t r;
    asm("cvt.rna.tf32.f32 %0, %1;" : "=r"(r) : "f"(v));
    return r;
}
__device__ __forceinline__ void cp_async4(uint32_t saddr, const float* gptr) {
    asm volatile("cp.async.ca.shared.global [%0], [%1], 4;"
                 :: "r"(saddr), "l"(gptr));
}
__device__ __forceinline__ void cp_commit() {
    asm volatile("cp.async.commit_group;");
}
template <int N>
__device__ __forceinline__ void cp_wait() {
    asm volatile("cp.async.wait_group %0;" :: "n"(N));
}
// Fragment-pair permutation within each 8-wide k group: [0,2,4,6,1,3,5,7].
// Puts (tig, tig+4) adjacent -> each mma fragment loads as one float2.
__device__ __forceinline__ int permcol(int c) {
    return (c & ~7) | ((c & 3) << 1) | ((c >> 2) & 1);
}
// D += A(16x8) * B(8x8), tf32 in, f32 accum (fragment layout verified R9)
__device__ __forceinline__ void mma_tf32(float c[4], const uint32_t a[4],
                                         const uint32_t b[2]) {
    asm volatile(
        "mma.sync.aligned.m16n8k8.row.col.f32.tf32.tf32.f32 "
        "{%0,%1,%2,%3}, {%4,%5,%6,%7}, {%8,%9}, {%0,%1,%2,%3};"
        : "+f"(c[0]), "+f"(c[1]), "+f"(c[2]), "+f"(c[3])
        : "r"(a[0]), "r"(a[1]), "r"(a[2]), "r"(a[3]),
          "r"(b[0]), "r"(b[1]));
}

// ---------------------------------------------------------------------------
// Kernel 2: persistent tf32 implicit-GEMM, cp.async double-buffered im2col.
// CTA tile: 128 px x 64 oc, K=288 in 4 chunks of 72.
// 512 thr = 16 warps: warp(mr=w&7) rows mr*16..+15, (nc=w>>3) cols nc*32..+31.
// Copy mapping: r = tid&127 (fixed), sub = tid>>7 owns (cl,kh) pairs
// sub*6 .. sub*6+5 with cl = 2*sub + (j>=3), kh = j%3  (branch-free).
// ---------------------------------------------------------------------------
__global__ __launch_bounds__(512, 1)
void conv_mma(const float* __restrict__ x,
              const float* __restrict__ bias,
              float* __restrict__ out) {
    extern __shared__ float sm[];
    float* Ws = sm + OFF_WS;
    int*   px = (int*)(sm + OFF_PX);

    const int tid = threadIdx.x;
    const int wid = tid >> 5;
    const int lid = tid & 31;
    const int gid = lid >> 2;
    const int tig = lid & 3;
    const int mr  = wid & 7;
    const int nc  = wid >> 3;

    // Copy-role constants (2 live regs)
    const int rr  = tid & 127;          // pixel row this thread copies
    const int sub = tid >> 7;           // 0..3: channel-pair group

    // Stage tf32 weights once per persistent CTA (permuted k layout)
    for (int i = tid; i < COUT * KTOT; i += 512) {
        int o = i / KTOT, k = i - o * KTOT;
        Ws[o * WS_STRIDE + permcol(k)] = to_tf32(g_kd[i]);
    }

    const uint32_t rowb0 = (uint32_t)__cvta_generic_to_shared(
        sm + OFF_AS + rr * AS_STRIDE);
    const uint32_t ABUF = AS_BUF_FLOATS * 4;
    __syncthreads();

    for (int T = blockIdx.x; T < NTILES; T += gridDim.x) {
        const int b     = T / NT_PER_B;
        const int tbase = (T % NT_PER_B) * TILE_M;
        const float* xb = x + (size_t)b * CIN * HH * WW;

        if (tid < TILE_M) {
            int p  = tbase + tid;
            int pp = (p < NPIX) ? p : 0;
            int ho = pp / WO;
            px[tid] = ho * WW + (pp - ho * WO);
        }
        __syncthreads();
        const int pxr = px[rr];         // cached: this thread's gmem pixel base

        // --- async im2col copy of chunk g into buffer g&1 (branch-free) ---
        auto copy_chunk = [&](int g) {
            const float* xc = xb + (size_t)g * CH_PER_CHUNK * HH * WW + pxr;
            const uint32_t bufb = rowb0 + (uint32_t)(g & 1) * ABUF;
            #pragma unroll
            for (int j = 0; j < 6; ++j) {
                const int cl = 2 * sub + (j >= 3 ? 1 : 0);
                const int kh = j % 3;                    // compile-time per j
                const float* gp = xc + cl * (HH * WW) + kh * WW;
                const int c0 = cl * 9 + kh * 3;
                cp_async4(bufb + (uint32_t)permcol(c0)     * 4u, gp);
                cp_async4(bufb + (uint32_t)permcol(c0 + 1) * 4u, gp + 1);
                cp_async4(bufb + (uint32_t)permcol(c0 + 2) * 4u, gp + 2);
            }
            cp_commit();
        };

        copy_chunk(0);

        float acc[4][4];
        #pragma unroll
        for (int n = 0; n < 4; ++n)
            #pragma unroll
            for (int q = 0; q < 4; ++q) acc[n][q] = 0.f;

        #pragma unroll
        for (int g = 0; g < NCHUNK; ++g) {
            if (g + 1 < NCHUNK) {
                copy_chunk(g + 1);
                cp_wait<1>();      // chunk g landed
            } else {
                cp_wait<0>();
            }
            __syncthreads();

            // --- mma phase on buffer g&1 (permuted float2 fragment loads) ---
            const float* As = sm + OFF_AS + (g & 1) * AS_BUF_FLOATS;
            const float* a0 = As + (mr * 16 + gid) * AS_STRIDE + 2 * tig;
            const float* a1 = a0 + 8 * AS_STRIDE;
            const float* wr0 = Ws + (nc * 32 + gid) * WS_STRIDE
                               + g * KCHUNK + 2 * tig;
            #pragma unroll
            for (int ks = 0; ks < 9; ++ks) {
                const int k0 = ks * 8;
                float2 lo = *(const float2*)(a0 + k0);
                float2 hi = *(const float2*)(a1 + k0);
                uint32_t a[4];
                a[0] = cvt_rna_u32(lo.x);
                a[2] = cvt_rna_u32(lo.y);
                a[1] = cvt_rna_u32(hi.x);
                a[3] = cvt_rna_u32(hi.y);
                #pragma unroll
                for (int nblk = 0; nblk < 4; ++nblk) {
                    float2 bf = *(const float2*)(wr0 + nblk * 8 * WS_STRIDE + k0);
                    uint32_t b2[2];
                    b2[0] = __float_as_uint(bf.x);
                    b2[1] = __float_as_uint(bf.y);
                    mma_tf32(acc[nblk], a, b2);
                }
            }
            __syncthreads();   // buffer g&1 free for g+2 prefetch
        }

        // --- epilogue: scatter C frags + bias ---
        const int p0 = tbase + mr * 16 + gid;
        const int p1 = p0 + 8;
        #pragma unroll
        for (int nblk = 0; nblk < 4; ++nblk) {
            const int col0 = nc * 32 + nblk * 8 + 2 * tig;
            const size_t ob0 = ((size_t)b * COUT + col0) * NPIX;
            const size_t bb0 = (size_t)col0 * NPIX;
            if (p0 < NPIX) {
                out[ob0 + p0]        = acc[nblk][0] + bias[bb0 + p0];
                out[ob0 + NPIX + p0] = acc[nblk][1] + bias[bb0 + NPIX + p0];
            }
            if (p1 < NPIX) {
                out[ob0 + p1]        = acc[nblk][2] + bias[bb0 + p1];
                out[ob0 + NPIX + p1] = acc[nblk][3] + bias[bb0 + NPIX + p1];
            }
        }
        __syncthreads();   // px rewrite next tile
    }
}

// ---------------------------------------------------------------------------
extern "C" void kernel_launch(void* const* d_in, const int* in_sizes, int n_in,
                              void* d_out, int out_size) {
    const float* x       = (const float*)d_in[0];  // [32,32,128,128]
    const float* weights = (const float*)d_in[1];  // [64,64,3,3]
    const float* bias    = (const float*)d_in[2];  // [64,126,126]
    const int*   cn      = (const int*)d_in[3];    // [64]
    float* out = (float*)d_out;                    // [32,64,126,126]

    static bool attr_set = false;
    if (!attr_set) {
        cudaFuncSetAttribute(conv_mma,
                             cudaFuncAttributeMaxDynamicSharedMemorySize,
                             SMEM_TOTAL);
        attr_set = true;
    }

    build_kdense<<<COUT, KTOT>>>(weights, cn);
    conv_mma<<<148, 512, SMEM_TOTAL>>>(x, bias, out);
}

// round 13
// speedup vs baseline: 1.3011x; 1.3011x over previous
#include <cuda_runtime.h>
#include <cuda_bf16.h>
#include <cstdint>

// ---------------------------------------------------------------------------
// Problem dims
// ---------------------------------------------------------------------------
#define BB    32
#define CIN   32
#define COUT  64
#define HH    128
#define WW    128
#define MAXCN 64
#define HO    126
#define WO    126
#define NPIX  (HO * WO)          // 15876
#define KTOT  (CIN * 9)          // 288
#define TILE_M 128
#define NT_PER_B ((NPIX + TILE_M - 1) / TILE_M)   // 125
#define NTILES (BB * NT_PER_B)                    // 4000
#define CH_PER_CHUNK 8
#define KCHUNK (CH_PER_CHUNK * 9)                 // 72
#define NCHUNK 4

#define WS_STRIDE 292     // floats per oc row (conflict-free scalar B loads)
#define AS_STRIDE 76      // floats per px row (conflict-free scalar A loads)
#define OFF_WS 0
#define OFF_AS (COUT * WS_STRIDE)                       // 18688 floats
#define AS_BUF_FLOATS (TILE_M * AS_STRIDE)              // 9728
#define OFF_PX (OFF_AS + 2 * AS_BUF_FLOATS)
#define SMEM_FLOATS (OFF_PX + TILE_M)
#define SMEM_TOTAL (SMEM_FLOATS * 4)                    // 153088 B

// Effective dense kernel scratch: [COUT][KTOT], k = c*9 + tap
__device__ float g_kd[COUT * KTOT];

// ---------------------------------------------------------------------------
// Kernel 1: fold padded kernel bank into dense [O, C*9]
// ---------------------------------------------------------------------------
__global__ void build_kdense(const float* __restrict__ w,
                             const int* __restrict__ cn) {
    int o = blockIdx.x;
    int t = threadIdx.x;
    if (t < KTOT) {
        int c = t / 9;
        int k = t % 9;
        int cnum = cn[o];
        float v = 0.f;
        if (c < cnum)        v += w[(o * MAXCN + c) * 9 + k];
        if (c + CIN < cnum)  v += w[(o * MAXCN + c + CIN) * 9 + k];
        g_kd[o * KTOT + t] = v;
    }
}

// ---------------------------------------------------------------------------
// helpers
// ---------------------------------------------------------------------------
__device__ __forceinline__ float to_tf32(float v) {
    uint32_t r;
    asm("cvt.rna.tf32.f32 %0, %1;" : "=r"(r) : "f"(v));
    return __uint_as_float(r);
}
__device__ __forceinline__ uint32_t cvt_rna_u32(float v) {
    uint32_t r;
    asm("cvt.rna.tf32.f32 %0, %1;" : "=r"(r) : "f"(v));
    return r;
}
__device__ __forceinline__ void cp_async4(uint32_t saddr, const float* gptr) {
    asm volatile("cp.async.ca.shared.global [%0], [%1], 4;"
                 :: "r"(saddr), "l"(gptr));
}
__device__ __forceinline__ void cp_commit() {
    asm volatile("cp.async.commit_group;");
}
template <int N>
__device__ __forceinline__ void cp_wait() {
    asm volatile("cp.async.wait_group %0;" :: "n"(N));
}
// D += A(16x8) * B(8x8), tf32 in, f32 accum (fragment layout verified R9)
__device__ __forceinline__ void mma_tf32(float c[4], const uint32_t a[4],
                                         const uint32_t b[2]) {
    asm volatile(
        "mma.sync.aligned.m16n8k8.row.col.f32.tf32.tf32.f32 "
        "{%0,%1,%2,%3}, {%4,%5,%6,%7}, {%8,%9}, {%0,%1,%2,%3};"
        : "+f"(c[0]), "+f"(c[1]), "+f"(c[2]), "+f"(c[3])
        : "r"(a[0]), "r"(a[1]), "r"(a[2]), "r"(a[3]),
          "r"(b[0]), "r"(b[1]));
}

// ---------------------------------------------------------------------------
// Kernel 2: persistent tf32 implicit-GEMM, cp.async double-buffered im2col,
// register-double-buffered (software pipelined) ks loop.
// CTA tile: 128 px x 64 oc, K=288 in 4 chunks of 72.
// 512 thr = 16 warps: warp(mr=w&7) rows mr*16..+15, (nc=w>>3) cols nc*32..+31.
// ---------------------------------------------------------------------------
__global__ __launch_bounds__(512, 1)
void conv_mma(const float* __restrict__ x,
              const float* __restrict__ bias,
              float* __restrict__ out) {
    extern __shared__ float sm[];
    float* Ws = sm + OFF_WS;
    int*   px = (int*)(sm + OFF_PX);

    const int tid = threadIdx.x;
    const int wid = tid >> 5;
    const int lid = tid & 31;
    const int gid = lid >> 2;
    const int tig = lid & 3;
    const int mr  = wid & 7;
    const int nc  = wid >> 3;

    // Copy-role constants (branch-free mapping, cheap)
    const int rr  = tid & 127;          // pixel row this thread copies
    const int sub = tid >> 7;           // 0..3: channel-pair group

    // Stage tf32 weights once per persistent CTA (natural k layout)
    for (int i = tid; i < COUT * KTOT; i += 512) {
        int o = i / KTOT, k = i - o * KTOT;
        Ws[o * WS_STRIDE + k] = to_tf32(g_kd[i]);
    }

    const uint32_t rowb0 = (uint32_t)__cvta_generic_to_shared(
        sm + OFF_AS + rr * AS_STRIDE);
    const uint32_t ABUF = AS_BUF_FLOATS * 4;
    __syncthreads();

    for (int T = blockIdx.x; T < NTILES; T += gridDim.x) {
        const int b     = T / NT_PER_B;
        const int tbase = (T % NT_PER_B) * TILE_M;
        const float* xb = x + (size_t)b * CIN * HH * WW;

        if (tid < TILE_M) {
            int p  = tbase + tid;
            int pp = (p < NPIX) ? p : 0;
            int ho = pp / WO;
            px[tid] = ho * WW + (pp - ho * WO);
        }
        __syncthreads();
        const int pxr = px[rr];

        // --- async im2col copy of chunk g into buffer g&1 (branch-free) ---
        auto copy_chunk = [&](int g) {
            const float* xc = xb + (size_t)g * CH_PER_CHUNK * HH * WW + pxr;
            const uint32_t bufb = rowb0 + (uint32_t)(g & 1) * ABUF;
            #pragma unroll
            for (int j = 0; j < 6; ++j) {
                const int cl = 2 * sub + (j >= 3 ? 1 : 0);
                const int kh = j % 3;                     // compile-time per j
                const float* gp = xc + cl * (HH * WW) + kh * WW;
                const uint32_t sa = bufb + (uint32_t)(cl * 9 + kh * 3) * 4u;
                cp_async4(sa,     gp);
                cp_async4(sa + 4, gp + 1);
                cp_async4(sa + 8, gp + 2);
            }
            cp_commit();
        };

        copy_chunk(0);

        float acc[4][4];
        #pragma unroll
        for (int n = 0; n < 4; ++n)
            #pragma unroll
            for (int q = 0; q < 4; ++q) acc[n][q] = 0.f;

        #pragma unroll
        for (int g = 0; g < NCHUNK; ++g) {
            if (g + 1 < NCHUNK) {
                copy_chunk(g + 1);
                cp_wait<1>();      // chunk g landed
            } else {
                cp_wait<0>();
            }
            __syncthreads();

            // --- mma phase, ks software-pipelined in registers ---
            const float* As = sm + OFF_AS + (g & 1) * AS_BUF_FLOATS;
            const float* a0 = As + (mr * 16 + gid) * AS_STRIDE + tig;
            const float* a1 = a0 + 8 * AS_STRIDE;
            const float* wr0 = Ws + (nc * 32 + gid) * WS_STRIDE
                               + g * KCHUNK + tig;

            float aC[4], bC[4][2];
            // preload ks = 0
            aC[0] = a0[0];  aC[1] = a1[0];
            aC[2] = a0[4];  aC[3] = a1[4];
            #pragma unroll
            for (int nblk = 0; nblk < 4; ++nblk) {
                const float* wr = wr0 + nblk * 8 * WS_STRIDE;
                bC[nblk][0] = wr[0];
                bC[nblk][1] = wr[4];
            }

            #pragma unroll
            for (int ks = 0; ks < 9; ++ks) {
                float aN[4], bN[4][2];
                if (ks < 8) {              // prefetch ks+1 while mmas run
                    const int k1 = (ks + 1) * 8;
                    aN[0] = a0[k1];      aN[1] = a1[k1];
                    aN[2] = a0[k1 + 4];  aN[3] = a1[k1 + 4];
                    #pragma unroll
                    for (int nblk = 0; nblk < 4; ++nblk) {
                        const float* wr = wr0 + nblk * 8 * WS_STRIDE + k1;
                        bN[nblk][0] = wr[0];
                        bN[nblk][1] = wr[4];
                    }
                }
                uint32_t a[4];
                a[0] = cvt_rna_u32(aC[0]);
                a[1] = cvt_rna_u32(aC[1]);
                a[2] = cvt_rna_u32(aC[2]);
                a[3] = cvt_rna_u32(aC[3]);
                #pragma unroll
                for (int nblk = 0; nblk < 4; ++nblk) {
                    uint32_t b2[2];
                    b2[0] = __float_as_uint(bC[nblk][0]);
                    b2[1] = __float_as_uint(bC[nblk][1]);
                    mma_tf32(acc[nblk], a, b2);
                }
                if (ks < 8) {
                    #pragma unroll
                    for (int q = 0; q < 4; ++q) aC[q] = aN[q];
                    #pragma unroll
                    for (int nblk = 0; nblk < 4; ++nblk) {
                        bC[nblk][0] = bN[nblk][0];
                        bC[nblk][1] = bN[nblk][1];
                    }
                }
            }
            __syncthreads();   // buffer g&1 free for g+2 prefetch
        }

        // --- epilogue: scatter C frags + bias ---
        const int p0 = tbase + mr * 16 + gid;
        const int p1 = p0 + 8;
        #pragma unroll
        for (int nblk = 0; nblk < 4; ++nblk) {
            const int col0 = nc * 32 + nblk * 8 + 2 * tig;
            const size_t ob0 = ((size_t)b * COUT + col0) * NPIX;
            const size_t bb0 = (size_t)col0 * NPIX;
            if (p0 < NPIX) {
                out[ob0 + p0]        = acc[nblk][0] + bias[bb0 + p0];
                out[ob0 + NPIX + p0] = acc[nblk][1] + bias[bb0 + NPIX + p0];
            }
            if (p1 < NPIX) {
                out[ob0 + p1]        = acc[nblk][2] + bias[bb0 + p1];
                out[ob0 + NPIX + p1] = acc[nblk][3] + bias[bb0 + NPIX + p1];
            }
        }
        __syncthreads();   // px rewrite next tile
    }
}

// ---------------------------------------------------------------------------
extern "C" void kernel_launch(void* const* d_in, const int* in_sizes, int n_in,
                              void* d_out, int out_size) {
    const float* x       = (const float*)d_in[0];  // [32,32,128,128]
    const float* weights = (const float*)d_in[1];  // [64,64,3,3]
    const float* bias    = (const float*)d_in[2];  // [64,126,126]
    const int*   cn      = (const int*)d_in[3];    // [64]
    float* out = (float*)d_out;                    // [32,64,126,126]

    static bool attr_set = false;
    if (!attr_set) {
        cudaFuncSetAttribute(conv_mma,
                             cudaFuncAttributeMaxDynamicSharedMemorySize,
                             SMEM_TOTAL);
        attr_set = true;
    }

    build_kdense<<<COUT, KTOT>>>(weights, cn);
    conv_mma<<<148, 512, SMEM_TOTAL>>>(x, bias, out);
}

// round 16
// speedup vs baseline: 1.4362x; 1.1038x over previous
#include <cuda_runtime.h>
#include <cuda_bf16.h>
#include <cstdint>

// ---------------------------------------------------------------------------
// Problem dims
// ---------------------------------------------------------------------------
#define BB    32
#define CIN   32
#define COUT  64
#define HH    128
#define WW    128
#define MAXCN 64
#define HO    126
#define WO    126
#define NPIX  (HO * WO)          // 15876
#define KTOT  (CIN * 9)          // 288
#define TILE_M 64
#define NT_PER_B ((NPIX + TILE_M - 1) / TILE_M)   // 249
#define NTILES (BB * NT_PER_B)                    // 7968
#define CH_PER_CHUNK 8
#define KCHUNK (CH_PER_CHUNK * 9)                 // 72
#define NCHUNK 4

#define WS_STRIDE 292     // floats per oc row (conflict-free scalar B loads)
#define AS_STRIDE 76      // floats per px row (conflict-free scalar A loads)
#define OFF_WS 0
#define OFF_AS (COUT * WS_STRIDE)                 // 18688 floats
#define AS_BUF_FLOATS (TILE_M * AS_STRIDE)        // 4864
#define AS_GRP_FLOATS (2 * AS_BUF_FLOATS)         // 9728 (double buffer)
#define SMEM_FLOATS (OFF_AS + 2 * AS_GRP_FLOATS)  // 38144
#define SMEM_TOTAL (SMEM_FLOATS * 4)              // 152576 B

// Effective dense kernel scratch: [COUT][KTOT], k = c*9 + tap
__device__ float g_kd[COUT * KTOT];

// ---------------------------------------------------------------------------
// Kernel 1: fold padded kernel bank into dense [O, C*9]
// ---------------------------------------------------------------------------
__global__ void build_kdense(const float* __restrict__ w,
                             const int* __restrict__ cn) {
    int o = blockIdx.x;
    int t = threadIdx.x;
    if (t < KTOT) {
        int c = t / 9;
        int k = t % 9;
        int cnum = cn[o];
        float v = 0.f;
        if (c < cnum)        v += w[(o * MAXCN + c) * 9 + k];
        if (c + CIN < cnum)  v += w[(o * MAXCN + c + CIN) * 9 + k];
        g_kd[o * KTOT + t] = v;
    }
}

// ---------------------------------------------------------------------------
// helpers
// ---------------------------------------------------------------------------
__device__ __forceinline__ float to_tf32(float v) {
    uint32_t r;
    asm("cvt.rna.tf32.f32 %0, %1;" : "=r"(r) : "f"(v));
    return __uint_as_float(r);
}
__device__ __forceinline__ uint32_t cvt_rna_u32(float v) {
    uint32_t r;
    asm("cvt.rna.tf32.f32 %0, %1;" : "=r"(r) : "f"(v));
    return r;
}
__device__ __forceinline__ void cp_async4(uint32_t saddr, const float* gptr) {
    asm volatile("cp.async.ca.shared.global [%0], [%1], 4;"
                 :: "r"(saddr), "l"(gptr));
}
__device__ __forceinline__ void cp_commit() {
    asm volatile("cp.async.commit_group;");
}
template <int N>
__device__ __forceinline__ void cp_wait() {
    asm volatile("cp.async.wait_group %0;" :: "n"(N));
}
__device__ __forceinline__ void bar_grp(int id) {       // 256-thread group sync
    asm volatile("bar.sync %0, 256;" :: "r"(id) : "memory");
}
// D += A(16x8) * B(8x8), tf32 in, f32 accum (fragment layout verified R9)
__device__ __forceinline__ void mma_tf32(float c[4], const uint32_t a[4],
                                         const uint32_t b[2]) {
    asm volatile(
        "mma.sync.aligned.m16n8k8.row.col.f32.tf32.tf32.f32 "
        "{%0,%1,%2,%3}, {%4,%5,%6,%7}, {%8,%9}, {%0,%1,%2,%3};"
        : "+f"(c[0]), "+f"(c[1]), "+f"(c[2]), "+f"(c[3])
        : "r"(a[0]), "r"(a[1]), "r"(a[2]), "r"(a[3]),
          "r"(b[0]), "r"(b[1]));
}

// ---------------------------------------------------------------------------
// Kernel 2: persistent tf32 implicit-GEMM; ONE CTA = TWO independent
// 256-thread tile-groups with private named barriers and private As double
// buffers; Ws shared. Group tile: 64 px x 64 oc, K=288 in 4 chunks of 72.
// Group = 8 warps: mr = gw&3 (rows mr*16..+15), nc = gw>>2 (cols nc*32..+31).
// ---------------------------------------------------------------------------
__global__ __launch_bounds__(512, 1)
void conv_mma(const float* __restrict__ x,
              const float* __restrict__ bias,
              float* __restrict__ out) {
    extern __shared__ float sm[];
    float* Ws = sm + OFF_WS;

    const int tid   = threadIdx.x;
    const int grp   = tid >> 8;          // 0 or 1
    const int gtid  = tid & 255;
    const int gw    = gtid >> 5;         // warp within group (0..7)
    const int lid   = tid & 31;
    const int gid   = lid >> 2;
    const int tig   = lid & 3;
    const int mr    = gw & 3;
    const int nc    = gw >> 2;
    const int barid = 1 + grp;

    // Copy role: rr = own pixel row (0..63), sub = channel-pair group (0..3)
    const int rr  = gtid & 63;
    const int sub = gtid >> 6;

    // Stage tf32 weights once (all 512 threads)
    for (int i = tid; i < COUT * KTOT; i += 512) {
        int o = i / KTOT, k = i - o * KTOT;
        Ws[o * WS_STRIDE + k] = to_tf32(g_kd[i]);
    }

    float* as_grp = sm + OFF_AS + grp * AS_GRP_FLOATS;
    const uint32_t rowb0 = (uint32_t)__cvta_generic_to_shared(
        as_grp + rr * AS_STRIDE);
    const uint32_t ABUF = AS_BUF_FLOATS * 4;
    __syncthreads();     // Ws visible to everyone; only group barriers after

    for (int T = blockIdx.x * 2 + grp; T < NTILES; T += 2 * gridDim.x) {
        const int b     = T / NT_PER_B;
        const int tbase = (T % NT_PER_B) * TILE_M;
        const float* xb = x + (size_t)b * CIN * HH * WW;

        // Own-row pixel offset (no smem table, no extra barrier)
        int pxr;
        {
            int p  = tbase + rr;
            int pp = (p < NPIX) ? p : 0;
            int ho = pp / WO;
            pxr = ho * WW + (pp - ho * WO);
        }

        auto copy_chunk = [&](int g) {
            const float* xc = xb + (size_t)g * CH_PER_CHUNK * HH * WW + pxr;
            const uint32_t bufb = rowb0 + (uint32_t)(g & 1) * ABUF;
            #pragma unroll
            for (int j = 0; j < 6; ++j) {
                const int cl = 2 * sub + (j >= 3 ? 1 : 0);
                const int kh = j % 3;                    // compile-time per j
                const float* gp = xc + cl * (HH * WW) + kh * WW;
                const uint32_t sa = bufb + (uint32_t)(cl * 9 + kh * 3) * 4u;
                cp_async4(sa,     gp);
                cp_async4(sa + 4, gp + 1);
                cp_async4(sa + 8, gp + 2);
            }
            cp_commit();
        };

        copy_chunk(0);

        float acc[4][4];
        #pragma unroll
        for (int n = 0; n < 4; ++n)
            #pragma unroll
            for (int q = 0; q < 4; ++q) acc[n][q] = 0.f;

        #pragma unroll
        for (int g = 0; g < NCHUNK; ++g) {
            if (g + 1 < NCHUNK) {
                copy_chunk(g + 1);
                cp_wait<1>();      // chunk g landed
            } else {
                cp_wait<0>();
            }
            bar_grp(barid);

            // --- mma phase, ks software-pipelined in registers ---
            const float* As = as_grp + (g & 1) * AS_BUF_FLOATS;
            const float* a0 = As + (mr * 16 + gid) * AS_STRIDE + tig;
            const float* a1 = a0 + 8 * AS_STRIDE;
            const float* wr0 = Ws + (nc * 32 + gid) * WS_STRIDE
                               + g * KCHUNK + tig;

            float aC[4], bC[4][2];
            aC[0] = a0[0];  aC[1] = a1[0];
            aC[2] = a0[4];  aC[3] = a1[4];
            #pragma unroll
            for (int nblk = 0; nblk < 4; ++nblk) {
                const float* wr = wr0 + nblk * 8 * WS_STRIDE;
                bC[nblk][0] = wr[0];
                bC[nblk][1] = wr[4];
            }

            #pragma unroll
            for (int ks = 0; ks < 9; ++ks) {
                float aN[4], bN[4][2];
                if (ks < 8) {              // prefetch ks+1 while mmas run
                    const int k1 = (ks + 1) * 8;
                    aN[0] = a0[k1];      aN[1] = a1[k1];
                    aN[2] = a0[k1 + 4];  aN[3] = a1[k1 + 4];
                    #pragma unroll
                    for (int nblk = 0; nblk < 4; ++nblk) {
                        const float* wr = wr0 + nblk * 8 * WS_STRIDE + k1;
                        bN[nblk][0] = wr[0];
                        bN[nblk][1] = wr[4];
                    }
                }
                uint32_t a[4];
                a[0] = cvt_rna_u32(aC[0]);
                a[1] = cvt_rna_u32(aC[1]);
                a[2] = cvt_rna_u32(aC[2]);
                a[3] = cvt_rna_u32(aC[3]);
                #pragma unroll
                for (int nblk = 0; nblk < 4; ++nblk) {
                    uint32_t b2[2];
                    b2[0] = __float_as_uint(bC[nblk][0]);
                    b2[1] = __float_as_uint(bC[nblk][1]);
                    mma_tf32(acc[nblk], a, b2);
                }
                if (ks < 8) {
                    #pragma unroll
                    for (int q = 0; q < 4; ++q) aC[q] = aN[q];
                    #pragma unroll
                    for (int nblk = 0; nblk < 4; ++nblk) {
                        bC[nblk][0] = bN[nblk][0];
                        bC[nblk][1] = bN[nblk][1];
                    }
                }
            }
            bar_grp(barid);    // buffer g&1 free for the g+2 copy
        }

        // --- epilogue: scatter C frags + bias (gmem only, no barrier) ---
        const int p0 = tbase + mr * 16 + gid;
        const int p1 = p0 + 8;
        #pragma unroll
        for (int nblk = 0; nblk < 4; ++nblk) {
            const int col0 = nc * 32 + nblk * 8 + 2 * tig;
            const size_t ob0 = ((size_t)b * COUT + col0) * NPIX;
            const size_t bb0 = (size_t)col0 * NPIX;
            if (p0 < NPIX) {
                out[ob0 + p0]        = acc[nblk][0] + bias[bb0 + p0];
                out[ob0 + NPIX + p0] = acc[nblk][1] + bias[bb0 + NPIX + p0];
            }
            if (p1 < NPIX) {
                out[ob0 + p1]        = acc[nblk][2] + bias[bb0 + p1];
                out[ob0 + NPIX + p1] = acc[nblk][3] + bias[bb0 + NPIX + p1];
            }
        }
    }
}

// ---------------------------------------------------------------------------
extern "C" void kernel_launch(void* const* d_in, const int* in_sizes, int n_in,
                              void* d_out, int out_size) {
    const float* x       = (const float*)d_in[0];  // [32,32,128,128]
    const float* weights = (const float*)d_in[1];  // [64,64,3,3]
    const float* bias    = (const float*)d_in[2];  // [64,126,126]
    const int*   cn      = (const int*)d_in[3];    // [64]
    float* out = (float*)d_out;                    // [32,64,126,126]

    static bool attr_set = false;
    if (!attr_set) {
        cudaFuncSetAttribute(conv_mma,
                             cudaFuncAttributeMaxDynamicSharedMemorySize,
                             SMEM_TOTAL);
        attr_set = true;
    }

    build_kdense<<<COUT, KTOT>>>(weights, cn);
    conv_mma<<<148, 512, SMEM_TOTAL>>>(x, bias, out);
}